// round 17
// baseline (speedup 1.0000x reference)
#include <cuda_runtime.h>
#include <cuda_bf16.h>
#include <mma.h>
#include <cstdint>

using namespace nvcuda;

#define N_NODES 40000
#define D_IN    512
#define D_OUT   128
#define N_EDGES 640000
#define CAP     64      // slots per row bucket; P(degree>64) ~ 2e-22 for Poisson(16)

// Device scratch (no allocs allowed). All zero-initialized at module load;
// every kernel that dirties persistent state restores it before exit, so
// graph replays are deterministic.
__device__ float4        g_seq[N_NODES * 32];     // seq = X @ W^T, 20.5 MB
__device__ int           g_cnt[N_NODES];          // per-row degree (zeroed by gather)
__device__ uint2         g_edges[N_NODES * CAP];  // packed (col, val) per bucket slot
__device__ __nv_bfloat16 g_wh[D_OUT * D_IN];      // W hi split (bf16)
__device__ __nv_bfloat16 g_wl[D_OUT * D_IN];      // W lo split (bf16)
__device__ int           g_tile;                  // work queue cursor  (reset on exit)
__device__ int           g_wsplit_done;           // W-split completion (reset on exit)
__device__ int           g_exit;                  // CTA exit counter   (reset on exit)

// ===========================================================================
// Fused persistent kernel. Work queue (in order):
//   [0, 8)        W-split slices: split 8192 W elems to bf16 hi/lo AND zero
//                 1/8 of the g_seq tail rows (37888..39999, used by red.add
//                 eighth-tiles). Signals g_wsplit_done.
//   [8, 296)      288 edge-place chunks (2223 edges each) — keeps every CTA
//                 busy while W-split finishes; independent of W.
//   [296, 888)    592 full GEMM tiles, 64 rows x 128 cols (rows 0..37887).
//   [888, 1152)   264 eighth tiles (33 row-blocks x 8 K-pieces of K=64),
//                 ~1/8 cost: they fill the makespan tail; red.add into the
//                 pre-zeroed g_seq tail.
// GEMM items spin on g_wsplit_done==8 (sub-microsecond; place work covers it).
//
// GEMM: seq = X @ W^T via bf16x3 split on WMMA. 256 threads = 8 warps (2x4),
// warp = 32x32 (2x2 m16n16k16 frags). K chunks of 32, double-buffered smem.
// __launch_bounds__(256,2) + 61KB smem -> 2 CTAs/SM.
// acc += Ahi*Bhi + Ahi*Blo + Alo*Bhi  (lo*lo ~2^-16 rel, dropped).
// ===========================================================================
#define KC        32
#define LDA       40                          // bf16 elems per row (+8 pad)
#define TILE_A    (64  * LDA)                 // 2560 elems
#define TILE_B    (128 * LDA)                 // 5120 elems
#define BUF_ELEM  (2 * TILE_A + 2 * TILE_B)   // 15360 elems
#define SMEM_GEMM (2 * BUF_ELEM * 2)          // 61440 bytes

#define QROW0        37888                    // first row owned by eighth tiles
#define WSPLIT_ITEMS 8
#define WSPLIT_ELEMS (D_OUT * D_IN / WSPLIT_ITEMS)        // 8192
#define TAILF4_PER   ((2112 * D_OUT / 4) / WSPLIT_ITEMS)  // 8448 float4 per slice
#define PLACE_CHUNKS 288
#define EDGES_PER_CH 2223                     // 288*2223 = 640224 >= N_EDGES
#define N_FULL       592
#define N_EIGHTH     264                      // 33 row-blocks * 8 K-pieces
#define ITEM_PLACE0  WSPLIT_ITEMS
#define ITEM_FULL0   (WSPLIT_ITEMS + PLACE_CHUNKS)        // 296
#define ITEM_EIGHTH0 (ITEM_FULL0 + N_FULL)                // 888
#define N_ITEMS      (ITEM_EIGHTH0 + N_EIGHTH)            // 1152
#define GEMM_CTAS    296

__global__ __launch_bounds__(256, 2) void fused_kernel(const float* __restrict__ x,
                                                       const float* __restrict__ w,
                                                       const float* __restrict__ ev,
                                                       const int*   __restrict__ er,
                                                       const int*   __restrict__ ec)
{
    extern __shared__ __nv_bfloat16 sm[];
    __shared__ int s_item;
    const int tid = threadIdx.x;
    const int wid = tid >> 5;
    const int wm  = wid >> 2;              // 0..1: rows wm*32
    const int wn  = wid & 3;               // 0..3: cols wn*32

    // A loads: 64 rows x 8 quads = 512 float4; 2 per thread
    const int ra0 = tid >> 3,         qa0 = tid & 7;
    const int ra1 = (tid + 256) >> 3, qa1 = (tid + 256) & 7;
    // B loads: 128 rows x 4 uint4 per (hi|lo); 2 each per thread
    const int rb0 = tid >> 2,         qb0 = tid & 3;
    const int rb1 = (tid + 256) >> 2, qb1 = (tid + 256) & 3;

    float* seqf = (float*)g_seq;

    for (;;) {
        if (tid == 0) s_item = atomicAdd(&g_tile, 1);
        __syncthreads();
        const int item = s_item;
        if (item >= N_ITEMS) break;

        if (item < WSPLIT_ITEMS) {
            // ---- W-split slice + seq-tail zero slice ----
            const int base = item * WSPLIT_ELEMS;
            for (int t = tid; t < WSPLIT_ELEMS; t += 256) {
                int idx = base + t;
                float f = w[idx];
                __nv_bfloat16 h = __float2bfloat16_rn(f);
                g_wh[idx] = h;
                g_wl[idx] = __float2bfloat16_rn(f - __bfloat162float(h));
            }
            float4* tz = (float4*)(seqf + (size_t)QROW0 * D_OUT) + item * TAILF4_PER;
            for (int t = tid; t < TAILF4_PER; t += 256)
                tz[t] = make_float4(0.f, 0.f, 0.f, 0.f);
            __syncthreads();
            if (tid == 0) { __threadfence(); atomicAdd(&g_wsplit_done, 1); }
            continue;
        }

        if (item < ITEM_FULL0) {
            // ---- edge placement chunk ----
            const int e0 = (item - ITEM_PLACE0) * EDGES_PER_CH;
            const int e1 = min(N_EDGES, e0 + EDGES_PER_CH);
            for (int e = e0 + tid; e < e1; e += 256) {
                int r = er[e];
                int p = atomicAdd(&g_cnt[r], 1);
                if (p < CAP)
                    g_edges[r * CAP + p] =
                        make_uint2((unsigned)ec[e], __float_as_uint(ev[e]));
            }
            continue;
        }

        // ---- GEMM tile (full or K-split eighth) — needs W split done ----
        if (tid == 0) while (atomicAdd(&g_wsplit_done, 0) < WSPLIT_ITEMS) { }
        __syncthreads();

        int blockRow, c0, c1;
        bool partial;
        if (item < ITEM_EIGHTH0) {
            blockRow = (item - ITEM_FULL0) * 64;             // rows 0..37887
            c0 = 0; c1 = D_IN / KC;                          // 16 chunks
            partial = false;
        } else {
            int q     = item - ITEM_EIGHTH0;                 // 0..263
            blockRow  = QROW0 + (q >> 3) * 64;               // rows 37888..39999
            c0        = (q & 7) * 2;                         // 2 chunks (K=64)
            c1        = c0 + 2;
            partial   = true;
        }

        wmma::fragment<wmma::accumulator, 16, 16, 16, float> acc[2][2];
        #pragma unroll
        for (int mi = 0; mi < 2; mi++)
            #pragma unroll
            for (int ni = 0; ni < 2; ni++) wmma::fill_fragment(acc[mi][ni], 0.f);

        // prefetch first chunk
        float4 fa0, fa1;
        uint4  vh0, vl0, vh1, vl1;
        {
            const int kt = c0 * KC;
            fa0 = ((const float4*)(x + (size_t)(blockRow + ra0) * D_IN + kt))[qa0];
            fa1 = ((const float4*)(x + (size_t)(blockRow + ra1) * D_IN + kt))[qa1];
            vh0 = *(const uint4*)(g_wh + rb0 * D_IN + kt + qb0 * 8);
            vl0 = *(const uint4*)(g_wl + rb0 * D_IN + kt + qb0 * 8);
            vh1 = *(const uint4*)(g_wh + rb1 * D_IN + kt + qb1 * 8);
            vl1 = *(const uint4*)(g_wl + rb1 * D_IN + kt + qb1 * 8);
        }

        for (int c = c0; c < c1; c++) {
            const int b = c & 1;
            __nv_bfloat16* Ah = sm + b * BUF_ELEM;
            __nv_bfloat16* Al = Ah + TILE_A;
            __nv_bfloat16* Bh = Al + TILE_A;
            __nv_bfloat16* Bl = Bh + TILE_B;

            // convert A hi/lo + store; copy B
            {
                float av[8] = {fa0.x, fa0.y, fa0.z, fa0.w, fa1.x, fa1.y, fa1.z, fa1.w};
                uint32_t hp[4], lp[4];
                #pragma unroll
                for (int p = 0; p < 4; p++) {
                    __nv_bfloat16 h0 = __float2bfloat16_rn(av[p * 2 + 0]);
                    __nv_bfloat16 h1 = __float2bfloat16_rn(av[p * 2 + 1]);
                    __nv_bfloat16 l0 = __float2bfloat16_rn(av[p * 2 + 0] - __bfloat162float(h0));
                    __nv_bfloat16 l1 = __float2bfloat16_rn(av[p * 2 + 1] - __bfloat162float(h1));
                    hp[p] = (uint32_t)__bfloat16_as_ushort(h0) | ((uint32_t)__bfloat16_as_ushort(h1) << 16);
                    lp[p] = (uint32_t)__bfloat16_as_ushort(l0) | ((uint32_t)__bfloat16_as_ushort(l1) << 16);
                }
                int ea0 = ra0 * LDA + qa0 * 4;
                int ea1 = ra1 * LDA + qa1 * 4;
                *(uint2*)(Ah + ea0) = make_uint2(hp[0], hp[1]);
                *(uint2*)(Al + ea0) = make_uint2(lp[0], lp[1]);
                *(uint2*)(Ah + ea1) = make_uint2(hp[2], hp[3]);
                *(uint2*)(Al + ea1) = make_uint2(lp[2], lp[3]);

                int eb0 = rb0 * LDA + qb0 * 8;
                int eb1 = rb1 * LDA + qb1 * 8;
                *(uint2*)(Bh + eb0)     = make_uint2(vh0.x, vh0.y);
                *(uint2*)(Bh + eb0 + 4) = make_uint2(vh0.z, vh0.w);
                *(uint2*)(Bl + eb0)     = make_uint2(vl0.x, vl0.y);
                *(uint2*)(Bl + eb0 + 4) = make_uint2(vl0.z, vl0.w);
                *(uint2*)(Bh + eb1)     = make_uint2(vh1.x, vh1.y);
                *(uint2*)(Bh + eb1 + 4) = make_uint2(vh1.z, vh1.w);
                *(uint2*)(Bl + eb1)     = make_uint2(vl1.x, vl1.y);
                *(uint2*)(Bl + eb1 + 4) = make_uint2(vl1.z, vl1.w);
            }
            __syncthreads();

            // prefetch next chunk (overlaps MMAs)
            if (c + 1 < c1) {
                const int kt = (c + 1) * KC;
                fa0 = ((const float4*)(x + (size_t)(blockRow + ra0) * D_IN + kt))[qa0];
                fa1 = ((const float4*)(x + (size_t)(blockRow + ra1) * D_IN + kt))[qa1];
                vh0 = *(const uint4*)(g_wh + rb0 * D_IN + kt + qb0 * 8);
                vl0 = *(const uint4*)(g_wl + rb0 * D_IN + kt + qb0 * 8);
                vh1 = *(const uint4*)(g_wh + rb1 * D_IN + kt + qb1 * 8);
                vl1 = *(const uint4*)(g_wl + rb1 * D_IN + kt + qb1 * 8);
            }

            // MMAs on buffer b
            #pragma unroll
            for (int ks = 0; ks < 2; ks++) {
                const int k0 = ks * 16;
                wmma::fragment<wmma::matrix_a, 16, 16, 16, __nv_bfloat16, wmma::row_major> fah[2], fal[2];
                wmma::fragment<wmma::matrix_b, 16, 16, 16, __nv_bfloat16, wmma::col_major> fbh[2], fbl[2];
                #pragma unroll
                for (int mi = 0; mi < 2; mi++) {
                    int r0 = wm * 32 + mi * 16;
                    wmma::load_matrix_sync(fah[mi], Ah + r0 * LDA + k0, LDA);
                    wmma::load_matrix_sync(fal[mi], Al + r0 * LDA + k0, LDA);
                }
                #pragma unroll
                for (int ni = 0; ni < 2; ni++) {
                    int cc = wn * 32 + ni * 16;
                    wmma::load_matrix_sync(fbh[ni], Bh + cc * LDA + k0, LDA);
                    wmma::load_matrix_sync(fbl[ni], Bl + cc * LDA + k0, LDA);
                }
                #pragma unroll
                for (int mi = 0; mi < 2; mi++)
                    #pragma unroll
                    for (int ni = 0; ni < 2; ni++) {
                        wmma::mma_sync(acc[mi][ni], fah[mi], fbh[ni], acc[mi][ni]);
                        wmma::mma_sync(acc[mi][ni], fah[mi], fbl[ni], acc[mi][ni]);
                        wmma::mma_sync(acc[mi][ni], fal[mi], fbh[ni], acc[mi][ni]);
                    }
            }
        }

        if (!partial) {
            // epilogue: fragments straight to g_seq
            #pragma unroll
            for (int mi = 0; mi < 2; mi++) {
                int row0 = blockRow + wm * 32 + mi * 16;
                #pragma unroll
                for (int ni = 0; ni < 2; ni++) {
                    int col0 = wn * 32 + ni * 16;
                    wmma::store_matrix_sync(seqf + (size_t)row0 * D_OUT + col0,
                                            acc[mi][ni], D_OUT, wmma::mem_row_major);
                }
            }
        } else {
            // epilogue: frags -> smem f32 tile -> red.global.add into g_seq
            float* sacc = (float*)sm;                 // 64x128 f32 = 32 KB
            __syncthreads();                          // all MMA smem reads done
            #pragma unroll
            for (int mi = 0; mi < 2; mi++) {
                int r0 = wm * 32 + mi * 16;
                #pragma unroll
                for (int ni = 0; ni < 2; ni++) {
                    int cc = wn * 32 + ni * 16;
                    wmma::store_matrix_sync(sacc + r0 * D_OUT + cc,
                                            acc[mi][ni], D_OUT, wmma::mem_row_major);
                }
            }
            __syncthreads();
            #pragma unroll
            for (int i = 0; i < 8; i++) {             // 2048 float4 / 256 thr
                int idx = i * 256 + tid;
                float4 v = ((const float4*)sacc)[idx];
                float* o = seqf + ((size_t)blockRow + (idx >> 5)) * D_OUT + (idx & 31) * 4;
                asm volatile("red.global.add.v4.f32 [%0], {%1, %2, %3, %4};"
                             :: "l"(o), "f"(v.x), "f"(v.y), "f"(v.z), "f"(v.w)
                             : "memory");
            }
        }
        // item-top atomic + __syncthreads is the barrier before smem reuse.
    }

    // Last CTA out restores queue/flag state for the next graph replay.
    if (tid == 0) {
        int v = atomicAdd(&g_exit, 1);
        if (v == GEMM_CTAS - 1) {
            g_tile = 0;
            g_wsplit_done = 0;
            g_exit = 0;
            __threadfence();
        }
    }
}

// ---------------------------------------------------------------------------
// Gather + bias + PReLU, fused. One warp per node; lane j owns features
// j*4..j*4+3 in registers. Zero atomics in the hot loop. Also re-zeroes
// g_cnt[node] for the next replay (deterministic: first run sees .bss zeros).
// ---------------------------------------------------------------------------
__global__ __launch_bounds__(256) void gather_kernel(const float*  __restrict__ bias,
                                                     const float*  __restrict__ alpha,
                                                     float4*       __restrict__ out)
{
    int gidx = blockIdx.x * blockDim.x + threadIdx.x;
    int node = gidx >> 5;
    int lane = gidx & 31;
    if (node >= N_NODES) return;

    int cnt = g_cnt[node];
    __syncwarp();
    if (lane == 0) g_cnt[node] = 0;
    cnt = cnt < CAP ? cnt : CAP;
    const uint2* ep = &g_edges[node * CAP];

    float4 acc = reinterpret_cast<const float4*>(bias)[lane];

    int e = 0;
    for (; e + 1 < cnt; e += 2) {
        uint2 e0 = ep[e];
        uint2 e1 = ep[e + 1];
        float v0 = __uint_as_float(e0.y);
        float v1 = __uint_as_float(e1.y);
        float4 s0 = g_seq[e0.x * 32 + lane];
        float4 s1 = g_seq[e1.x * 32 + lane];
        acc.x = fmaf(v0, s0.x, acc.x);
        acc.y = fmaf(v0, s0.y, acc.y);
        acc.z = fmaf(v0, s0.z, acc.z);
        acc.w = fmaf(v0, s0.w, acc.w);
        acc.x = fmaf(v1, s1.x, acc.x);
        acc.y = fmaf(v1, s1.y, acc.y);
        acc.z = fmaf(v1, s1.z, acc.z);
        acc.w = fmaf(v1, s1.w, acc.w);
    }
    if (e < cnt) {
        uint2 e0 = ep[e];
        float v0 = __uint_as_float(e0.y);
        float4 s0 = g_seq[e0.x * 32 + lane];
        acc.x = fmaf(v0, s0.x, acc.x);
        acc.y = fmaf(v0, s0.y, acc.y);
        acc.z = fmaf(v0, s0.z, acc.z);
        acc.w = fmaf(v0, s0.w, acc.w);
    }

    float a = alpha[0];
    acc.x = acc.x > 0.f ? acc.x : a * acc.x;
    acc.y = acc.y > 0.f ? acc.y : a * acc.y;
    acc.z = acc.z > 0.f ? acc.z : a * acc.z;
    acc.w = acc.w > 0.f ? acc.w : a * acc.w;

    out[node * 32 + lane] = acc;
}

// ---------------------------------------------------------------------------
// Launch. Inputs: x, weight, bias, alpha, edge_val, edge_row, edge_col.
// ---------------------------------------------------------------------------
extern "C" void kernel_launch(void* const* d_in, const int* in_sizes, int n_in,
                              void* d_out, int out_size)
{
    const float* x     = (const float*)d_in[0];
    const float* w     = (const float*)d_in[1];
    const float* bias  = (const float*)d_in[2];
    const float* alpha = (const float*)d_in[3];
    const float* ev    = (const float*)d_in[4];
    const int*   er    = (const int*)  d_in[5];
    const int*   ec    = (const int*)  d_in[6];
    float4*      out   = (float4*)d_out;

    cudaFuncSetAttribute(fused_kernel,
                         cudaFuncAttributeMaxDynamicSharedMemorySize, SMEM_GEMM);
    fused_kernel<<<GEMM_CTAS, 256, SMEM_GEMM>>>(x, w, ev, er, ec);

    {
        long long threads = (long long)N_NODES * 32;
        int blocks = (int)((threads + 255) / 256);
        gather_kernel<<<blocks, 256>>>(bias, alpha, out);
    }
}